// round 1
// baseline (speedup 1.0000x reference)
#include <cuda_runtime.h>
#include <math.h>

#define S 128
#define POS_BANDS 10
#define D_ENC 63      // 3 + 2*3*10
#define D_VD 27       // 3 + 2*3*4
#define HID 64
#define FEAT 15

__device__ float g_dt;

// ---------------------------------------------------------------------------
// Kernel A: dt = mean(tmax - tmin) / S  (deterministic single-block reduction)
// ---------------------------------------------------------------------------
__global__ void reduce_dt_kernel(const float* __restrict__ tmin,
                                 const float* __restrict__ tmax, int n) {
    __shared__ float sh[256];
    float s = 0.f;
    for (int i = threadIdx.x; i < n; i += 256) s += tmax[i] - tmin[i];
    sh[threadIdx.x] = s;
    __syncthreads();
    for (int o = 128; o > 0; o >>= 1) {
        if (threadIdx.x < o) sh[threadIdx.x] += sh[threadIdx.x + o];
        __syncthreads();
    }
    if (threadIdx.x == 0) g_dt = sh[0] / (float)n / (float)S;
}

// ---------------------------------------------------------------------------
// Kernel B: one block per ray, one thread per sample. Fully fused:
//   pos_enc -> MLP1(63->64) -> MLP2(64->16) -> color MLP(15(+folded vd)->64->3)
//   -> sigmoid -> transmittance scan -> weighted reduction
// ---------------------------------------------------------------------------
struct __align__(16) Smem {
    float W1[D_ENC * HID];   // 4032
    float W2[HID * 16];      // 1024
    float V1a[FEAT * HID];   // 960  (first 15 rows of V1)
    float V2p[HID * 4];      // 256  (V2 padded to float4 rows)
    float b1[HID];
    float base[HID];         // c1 + vd_enc @ V1[15:42]
    float b2[16];
    float c2[4];
    float vd[D_VD + 1];
    float scan[S];
    float red[16];           // 4 warps x 4 values
};

__global__ void __launch_bounds__(S, 3)
raymarch_kernel(const float* __restrict__ orig, const float* __restrict__ dirs,
                const float* __restrict__ tmin, const float* __restrict__ tmax,
                const float* __restrict__ W1, const float* __restrict__ b1,
                const float* __restrict__ W2, const float* __restrict__ b2,
                const float* __restrict__ V1, const float* __restrict__ c1,
                const float* __restrict__ V2, const float* __restrict__ c2,
                float* __restrict__ out, int N) {
    __shared__ Smem sm;
    const int r = blockIdx.x;
    const int s = threadIdx.x;

    // ---- stage weights to shared ----
    for (int i = s; i < D_ENC * HID; i += S) sm.W1[i] = W1[i];
    for (int i = s; i < HID * 16; i += S) sm.W2[i] = W2[i];
    for (int i = s; i < FEAT * HID; i += S) sm.V1a[i] = V1[i];
    if (s < HID) {
        sm.b1[s] = b1[s];
        sm.V2p[s * 4 + 0] = V2[s * 3 + 0];
        sm.V2p[s * 4 + 1] = V2[s * 3 + 1];
        sm.V2p[s * 4 + 2] = V2[s * 3 + 2];
        sm.V2p[s * 4 + 3] = 0.f;
    }
    if (s < 16) sm.b2[s] = b2[s];
    if (s < 4) sm.c2[s] = (s < 3) ? c2[s] : 0.f;

    // ---- per-ray constants ----
    const float dx = dirs[r * 3 + 0], dy = dirs[r * 3 + 1], dz = dirs[r * 3 + 2];
    const float inv = 1.f / (sqrtf(dx * dx + dy * dy + dz * dz) + 1e-8f);

    // view-dir encoding (27 values), one element per thread
    if (s < D_VD) {
        const int p = s / 3, c = s % 3;
        float v = ((c == 0) ? dx : (c == 1) ? dy : dz) * inv;
        float val;
        if (p == 0) {
            val = v;
        } else {
            const int band = (p - 1) >> 1;
            float sn, cs;
            sincosf(v * (float)(1 << band), &sn, &cs);
            val = ((p - 1) & 1) ? cs : sn;
        }
        sm.vd[s] = val;
    }
    __syncthreads();

    // base = c1 + vd_enc @ V1[15:42,:]  (per-ray constant of the color MLP)
    if (s < HID) {
        float acc = c1[s];
#pragma unroll
        for (int k = 0; k < D_VD; k++) acc += sm.vd[k] * V1[(FEAT + k) * HID + s];
        sm.base[s] = acc;
    }
    __syncthreads();

    // ---- per-sample position + encoding ----
    const float t0 = tmin[r], t1 = tmax[r];
    const float tt = t0 + (float)s * (1.f / (S - 1)) * (t1 - t0);
    const float px = orig[r * 3 + 0] + dx * tt;
    const float py = orig[r * 3 + 1] + dy * tt;
    const float pz = orig[r * 3 + 2] + dz * tt;

    float enc[D_ENC];
    enc[0] = px; enc[1] = py; enc[2] = pz;
#pragma unroll
    for (int b = 0; b < POS_BANDS; b++) {
        const float f = (float)(1 << b);
        float sn, cs;
        sincosf(f * px, &sn, &cs); enc[3 + 6 * b + 0] = sn; enc[6 + 6 * b + 0] = cs;
        sincosf(f * py, &sn, &cs); enc[3 + 6 * b + 1] = sn; enc[6 + 6 * b + 1] = cs;
        sincosf(f * pz, &sn, &cs); enc[3 + 6 * b + 2] = sn; enc[6 + 6 * b + 2] = cs;
    }

    // ---- MLP1: h = relu(enc @ W1 + b1) ----
    float h[HID];
#pragma unroll
    for (int j = 0; j < HID; j++) h[j] = sm.b1[j];
    const float4* W1_4 = (const float4*)sm.W1;
#pragma unroll
    for (int k = 0; k < D_ENC; k++) {
        const float e = enc[k];
#pragma unroll
        for (int j = 0; j < 16; j++) {
            const float4 w = W1_4[k * 16 + j];
            h[4 * j + 0] += e * w.x;
            h[4 * j + 1] += e * w.y;
            h[4 * j + 2] += e * w.z;
            h[4 * j + 3] += e * w.w;
        }
    }
#pragma unroll
    for (int j = 0; j < HID; j++) h[j] = fmaxf(h[j], 0.f);

    // ---- MLP2: o = h @ W2 + b2 ----
    float o[16];
#pragma unroll
    for (int j = 0; j < 16; j++) o[j] = sm.b2[j];
    const float4* W2_4 = (const float4*)sm.W2;
#pragma unroll
    for (int k = 0; k < HID; k++) {
        const float hv = h[k];
#pragma unroll
        for (int j = 0; j < 4; j++) {
            const float4 w = W2_4[k * 4 + j];
            o[4 * j + 0] += hv * w.x;
            o[4 * j + 1] += hv * w.y;
            o[4 * j + 2] += hv * w.z;
            o[4 * j + 3] += hv * w.w;
        }
    }
    const float sigma = fmaxf(o[0], 0.f);

    // ---- color MLP: g = base + rgb_feat @ V1[0:15,:] ----
    float g[HID];
#pragma unroll
    for (int j = 0; j < HID; j++) g[j] = sm.base[j];
    const float4* V1_4 = (const float4*)sm.V1a;
#pragma unroll
    for (int k = 0; k < FEAT; k++) {
        const float e = o[k + 1];
#pragma unroll
        for (int j = 0; j < 16; j++) {
            const float4 w = V1_4[k * 16 + j];
            g[4 * j + 0] += e * w.x;
            g[4 * j + 1] += e * w.y;
            g[4 * j + 2] += e * w.z;
            g[4 * j + 3] += e * w.w;
        }
    }

    // ---- rgb = sigmoid(relu(g) @ V2 + c2) ----
    float r0 = sm.c2[0], r1 = sm.c2[1], r2 = sm.c2[2];
    const float4* V2_4 = (const float4*)sm.V2p;
#pragma unroll
    for (int k = 0; k < HID; k++) {
        const float gv = fmaxf(g[k], 0.f);
        const float4 w = V2_4[k];
        r0 += gv * w.x;
        r1 += gv * w.y;
        r2 += gv * w.z;
    }
    r0 = 1.f / (1.f + expf(-r0));
    r1 = 1.f / (1.f + expf(-r1));
    r2 = 1.f / (1.f + expf(-r2));

    // ---- compositing: exclusive product scan over one_minus ----
    const float dtv = g_dt;
    const float om = expf(-sigma * dtv);     // 1 - alpha
    const float alpha = 1.f - om;

    sm.scan[s] = om;
    float x = om;
#pragma unroll
    for (int off = 1; off < S; off <<= 1) {
        __syncthreads();
        const float v = (s >= off) ? sm.scan[s - off] : 1.f;
        __syncthreads();
        x *= v;
        sm.scan[s] = x;
    }
    __syncthreads();
    const float Texcl = (s == 0) ? 1.f : sm.scan[s - 1];
    const bool active = (Texcl > 1e-4f);
    const float w = active ? Texcl * alpha : 0.f;

    float cr = w * r0, cg = w * r1, cb = w * r2;
    float tf = active ? om : 1.f;
#pragma unroll
    for (int off = 16; off; off >>= 1) {
        cr += __shfl_down_sync(0xffffffffu, cr, off);
        cg += __shfl_down_sync(0xffffffffu, cg, off);
        cb += __shfl_down_sync(0xffffffffu, cb, off);
        tf *= __shfl_down_sync(0xffffffffu, tf, off);
    }
    const int warp = s >> 5;
    if ((s & 31) == 0) {
        sm.red[warp * 4 + 0] = cr;
        sm.red[warp * 4 + 1] = cg;
        sm.red[warp * 4 + 2] = cb;
        sm.red[warp * 4 + 3] = tf;
    }
    __syncthreads();
    if (s == 0) {
        float R = sm.red[0] + sm.red[4] + sm.red[8] + sm.red[12];
        float G = sm.red[1] + sm.red[5] + sm.red[9] + sm.red[13];
        float B = sm.red[2] + sm.red[6] + sm.red[10] + sm.red[14];
        float T = sm.red[3] * sm.red[7] * sm.red[11] * sm.red[15];
        out[r * 3 + 0] = R;
        out[r * 3 + 1] = G;
        out[r * 3 + 2] = B;
        out[3 * N + r] = T;
    }
}

// ---------------------------------------------------------------------------
extern "C" void kernel_launch(void* const* d_in, const int* in_sizes, int n_in,
                              void* d_out, int out_size) {
    const float* orig = (const float*)d_in[0];
    const float* dirs = (const float*)d_in[1];
    const float* tmin = (const float*)d_in[2];
    const float* tmax = (const float*)d_in[3];
    const float* W1   = (const float*)d_in[4];
    const float* b1   = (const float*)d_in[5];
    const float* W2   = (const float*)d_in[6];
    const float* b2   = (const float*)d_in[7];
    const float* V1   = (const float*)d_in[8];
    const float* c1   = (const float*)d_in[9];
    const float* V2   = (const float*)d_in[10];
    const float* c2   = (const float*)d_in[11];
    float* out = (float*)d_out;
    const int N = in_sizes[2];   // tmin element count = number of rays

    reduce_dt_kernel<<<1, 256>>>(tmin, tmax, N);
    raymarch_kernel<<<N, S>>>(orig, dirs, tmin, tmax, W1, b1, W2, b2,
                              V1, c1, V2, c2, out, N);
}

// round 3
// speedup vs baseline: 1.0984x; 1.0984x over previous
#include <cuda_runtime.h>
#include <math.h>

#define SS 128
#define POS_BANDS 10
#define D_ENC 63
#define D_VD 27
#define HID 64
#define FEAT 15

__device__ float g_dt;

// ---------------- packed f32x2 FMA ----------------
struct F2 { union { float2 f; unsigned long long u; }; };
__device__ __forceinline__ F2 f2mk(float x, float y) { F2 r; r.f.x = x; r.f.y = y; return r; }
__device__ __forceinline__ F2 f2dup(float x) { return f2mk(x, x); }
__device__ __forceinline__ void fma2(F2& d, const F2 a, const F2 b) {
    asm("fma.rn.f32x2 %0, %1, %2, %0;" : "+l"(d.u) : "l"(a.u), "l"(b.u));
}

// ---------------------------------------------------------------------------
__global__ void reduce_dt_kernel(const float* __restrict__ tmin,
                                 const float* __restrict__ tmax, int n) {
    __shared__ float sh[256];
    float s = 0.f;
    for (int i = threadIdx.x; i < n; i += 256) s += tmax[i] - tmin[i];
    sh[threadIdx.x] = s;
    __syncthreads();
    for (int o = 128; o > 0; o >>= 1) {
        if (threadIdx.x < o) sh[threadIdx.x] += sh[threadIdx.x + o];
        __syncthreads();
    }
    if (threadIdx.x == 0) g_dt = sh[0] / (float)n / (float)SS;
}

// ---------------------------------------------------------------------------
struct __align__(16) SmemT {
    float bufA[64 * SS];   // ENC^T (rows k=0..62) -> later G^T (relu'd)
    float bufB[64 * SS];   // H^T
    float Ot[16 * SS];     // O^T (row 0 = raw sigma pre-relu)
    float W1s[64 * 64];    // rows 0..62 used, [k][j]
    float W2s[64 * 16];
    float V1s[16 * 64];    // rows 0..14
    float V2p[64 * 4];
    float b1s[64];
    float b2s[16];
    float basev[64];       // c1 + vd_enc @ V1[15:42]
    float c2s[4];
    float vd[28];
    float scan[SS];
    float red[16];
};

__global__ void __launch_bounds__(SS, 2)
raymarch_kernel(const float* __restrict__ orig, const float* __restrict__ dirs,
                const float* __restrict__ tmin, const float* __restrict__ tmax,
                const float* __restrict__ W1, const float* __restrict__ b1,
                const float* __restrict__ W2, const float* __restrict__ b2,
                const float* __restrict__ V1, const float* __restrict__ c1,
                const float* __restrict__ V2, const float* __restrict__ c2,
                float* __restrict__ out, int N) {
    extern __shared__ char smem_raw[];
    SmemT& sm = *reinterpret_cast<SmemT*>(smem_raw);
    const int r = blockIdx.x;
    const int tid = threadIdx.x;

    // ---- stage weights ----
    for (int i = tid; i < D_ENC * HID; i += SS) sm.W1s[i] = W1[i];
    for (int i = tid; i < HID * 16; i += SS) sm.W2s[i] = W2[i];
    for (int i = tid; i < FEAT * HID; i += SS) sm.V1s[i] = V1[i];
    if (tid < HID) {
        sm.b1s[tid] = b1[tid];
        sm.V2p[tid * 4 + 0] = V2[tid * 3 + 0];
        sm.V2p[tid * 4 + 1] = V2[tid * 3 + 1];
        sm.V2p[tid * 4 + 2] = V2[tid * 3 + 2];
        sm.V2p[tid * 4 + 3] = 0.f;
    }
    if (tid < 16) sm.b2s[tid] = b2[tid];
    if (tid < 4) sm.c2s[tid] = (tid < 3) ? c2[tid] : 0.f;

    const float dx = dirs[r * 3 + 0], dy = dirs[r * 3 + 1], dz = dirs[r * 3 + 2];
    const float inv = 1.f / (sqrtf(dx * dx + dy * dy + dz * dz) + 1e-8f);
    if (tid < D_VD) {
        const int p = tid / 3, c = tid % 3;
        float v = ((c == 0) ? dx : (c == 1) ? dy : dz) * inv;
        float val;
        if (p == 0) val = v;
        else {
            const int band = (p - 1) >> 1;
            float sn, cs;
            sincosf(v * (float)(1 << band), &sn, &cs);
            val = ((p - 1) & 1) ? cs : sn;
        }
        sm.vd[tid] = val;
    }
    __syncthreads();

    // ---- base = c1 + vd_enc @ V1[15:42]  (per-ray constant) ----
    if (tid < HID) {
        float acc = c1[tid];
#pragma unroll
        for (int k = 0; k < D_VD; k++) acc += sm.vd[k] * V1[(FEAT + k) * HID + tid];
        sm.basev[tid] = acc;
    }

    // ---- positional encoding -> ENC^T in bufA ----
    {
        const float t0 = tmin[r], t1 = tmax[r];
        const float tt = t0 + (float)tid * (1.f / (SS - 1)) * (t1 - t0);
        const float px = orig[r * 3 + 0] + dx * tt;
        const float py = orig[r * 3 + 1] + dy * tt;
        const float pz = orig[r * 3 + 2] + dz * tt;
        sm.bufA[0 * SS + tid] = px;
        sm.bufA[1 * SS + tid] = py;
        sm.bufA[2 * SS + tid] = pz;
#pragma unroll
        for (int b = 0; b < POS_BANDS; b++) {
            const float f = (float)(1 << b);
            float sn, cs;
            sincosf(f * px, &sn, &cs);
            sm.bufA[(3 + 6 * b + 0) * SS + tid] = sn;
            sm.bufA[(6 + 6 * b + 0) * SS + tid] = cs;
            sincosf(f * py, &sn, &cs);
            sm.bufA[(3 + 6 * b + 1) * SS + tid] = sn;
            sm.bufA[(6 + 6 * b + 1) * SS + tid] = cs;
            sincosf(f * pz, &sn, &cs);
            sm.bufA[(3 + 6 * b + 2) * SS + tid] = sn;
            sm.bufA[(6 + 6 * b + 2) * SS + tid] = cs;
        }
    }
    __syncthreads();

    // ======== Layer 1: H^T = relu(W1^T @ ENC)  [64 x 128] ========
    {
        const int cg = tid & 7, rg = tid >> 3;
        const int col0 = cg * 8, s0 = rg * 8;
        F2 acc[4][8];
#pragma unroll
        for (int j = 0; j < 8; j++) {
            const F2 bb = f2dup(sm.b1s[col0 + j]);
#pragma unroll
            for (int p = 0; p < 4; p++) acc[p][j] = bb;
        }
#pragma unroll 3
        for (int k = 0; k < D_ENC; k++) {
            const float4 a0 = *(const float4*)&sm.bufA[k * SS + s0];
            const float4 a1 = *(const float4*)&sm.bufA[k * SS + s0 + 4];
            const float4 w0 = *(const float4*)&sm.W1s[k * HID + col0];
            const float4 w1 = *(const float4*)&sm.W1s[k * HID + col0 + 4];
            F2 a[4] = {f2mk(a0.x, a0.y), f2mk(a0.z, a0.w), f2mk(a1.x, a1.y), f2mk(a1.z, a1.w)};
            const float wv[8] = {w0.x, w0.y, w0.z, w0.w, w1.x, w1.y, w1.z, w1.w};
#pragma unroll
            for (int j = 0; j < 8; j++) {
                const F2 bw = f2dup(wv[j]);
#pragma unroll
                for (int p = 0; p < 4; p++) fma2(acc[p][j], a[p], bw);
            }
        }
#pragma unroll
        for (int j = 0; j < 8; j++)
#pragma unroll
            for (int p = 0; p < 4; p++) {
                float2 v = acc[p][j].f;
                v.x = fmaxf(v.x, 0.f);
                v.y = fmaxf(v.y, 0.f);
                *(float2*)&sm.bufB[(col0 + j) * SS + s0 + 2 * p] = v;
            }
    }
    __syncthreads();

    // ======== Layer 2: O^T = W2^T @ H  [16 x 128] ========
    {
        const int cg = tid & 3, rg = tid >> 2;
        const int col0 = cg * 4, s0 = rg * 4;
        F2 acc[2][4];
#pragma unroll
        for (int j = 0; j < 4; j++) {
            const F2 bb = f2dup(sm.b2s[col0 + j]);
            acc[0][j] = bb; acc[1][j] = bb;
        }
#pragma unroll 4
        for (int k = 0; k < HID; k++) {
            const float4 a0 = *(const float4*)&sm.bufB[k * SS + s0];
            const float4 w0 = *(const float4*)&sm.W2s[k * 16 + col0];
            F2 a[2] = {f2mk(a0.x, a0.y), f2mk(a0.z, a0.w)};
            const float wv[4] = {w0.x, w0.y, w0.z, w0.w};
#pragma unroll
            for (int j = 0; j < 4; j++) {
                const F2 bw = f2dup(wv[j]);
                fma2(acc[0][j], a[0], bw);
                fma2(acc[1][j], a[1], bw);
            }
        }
#pragma unroll
        for (int j = 0; j < 4; j++) {
            *(float2*)&sm.Ot[(col0 + j) * SS + s0] = acc[0][j].f;
            *(float2*)&sm.Ot[(col0 + j) * SS + s0 + 2] = acc[1][j].f;
        }
    }
    __syncthreads();

    // ======== Layer 3: G^T = relu(base + V1a^T @ rgb_feat)  [64 x 128] ========
    {
        const int cg = tid & 7, rg = tid >> 3;
        const int col0 = cg * 8, s0 = rg * 8;
        F2 acc[4][8];
#pragma unroll
        for (int j = 0; j < 8; j++) {
            const F2 bb = f2dup(sm.basev[col0 + j]);
#pragma unroll
            for (int p = 0; p < 4; p++) acc[p][j] = bb;
        }
#pragma unroll
        for (int k = 0; k < FEAT; k++) {
            const float4 a0 = *(const float4*)&sm.Ot[(k + 1) * SS + s0];
            const float4 a1 = *(const float4*)&sm.Ot[(k + 1) * SS + s0 + 4];
            const float4 w0 = *(const float4*)&sm.V1s[k * HID + col0];
            const float4 w1 = *(const float4*)&sm.V1s[k * HID + col0 + 4];
            F2 a[4] = {f2mk(a0.x, a0.y), f2mk(a0.z, a0.w), f2mk(a1.x, a1.y), f2mk(a1.z, a1.w)};
            const float wv[8] = {w0.x, w0.y, w0.z, w0.w, w1.x, w1.y, w1.z, w1.w};
#pragma unroll
            for (int j = 0; j < 8; j++) {
                const F2 bw = f2dup(wv[j]);
#pragma unroll
                for (int p = 0; p < 4; p++) fma2(acc[p][j], a[p], bw);
            }
        }
#pragma unroll
        for (int j = 0; j < 8; j++)
#pragma unroll
            for (int p = 0; p < 4; p++) {
                float2 v = acc[p][j].f;
                v.x = fmaxf(v.x, 0.f);
                v.y = fmaxf(v.y, 0.f);
                *(float2*)&sm.bufA[(col0 + j) * SS + s0 + 2 * p] = v;
            }
    }
    __syncthreads();

    // ======== Layer 4 + compositing (per-sample) ========
    {
        const int s = tid;
        float r0 = sm.c2s[0], r1 = sm.c2s[1], r2 = sm.c2s[2];
#pragma unroll 8
        for (int k = 0; k < HID; k++) {
            const float g = sm.bufA[k * SS + s];
            const float4 w = *(const float4*)&sm.V2p[k * 4];
            r0 += g * w.x;
            r1 += g * w.y;
            r2 += g * w.z;
        }
        r0 = 1.f / (1.f + expf(-r0));
        r1 = 1.f / (1.f + expf(-r1));
        r2 = 1.f / (1.f + expf(-r2));

        const float sigma = fmaxf(sm.Ot[s], 0.f);
        const float dtv = g_dt;
        const float om = expf(-sigma * dtv);
        const float alpha = 1.f - om;

        sm.scan[s] = om;
        float x = om;
#pragma unroll
        for (int off = 1; off < SS; off <<= 1) {
            __syncthreads();
            const float v = (s >= off) ? sm.scan[s - off] : 1.f;
            __syncthreads();
            x *= v;
            sm.scan[s] = x;
        }
        __syncthreads();
        const float Texcl = (s == 0) ? 1.f : sm.scan[s - 1];
        const bool active = (Texcl > 1e-4f);
        const float w = active ? Texcl * alpha : 0.f;

        float cr = w * r0, cg2 = w * r1, cb = w * r2;
        float tf = active ? om : 1.f;
#pragma unroll
        for (int off = 16; off; off >>= 1) {
            cr  += __shfl_down_sync(0xffffffffu, cr,  off);
            cg2 += __shfl_down_sync(0xffffffffu, cg2, off);
            cb  += __shfl_down_sync(0xffffffffu, cb,  off);
            tf  *= __shfl_down_sync(0xffffffffu, tf,  off);
        }
        const int warp = s >> 5;
        if ((s & 31) == 0) {
            sm.red[warp * 4 + 0] = cr;
            sm.red[warp * 4 + 1] = cg2;
            sm.red[warp * 4 + 2] = cb;
            sm.red[warp * 4 + 3] = tf;
        }
        __syncthreads();
        if (s == 0) {
            out[r * 3 + 0] = sm.red[0] + sm.red[4] + sm.red[8] + sm.red[12];
            out[r * 3 + 1] = sm.red[1] + sm.red[5] + sm.red[9] + sm.red[13];
            out[r * 3 + 2] = sm.red[2] + sm.red[6] + sm.red[10] + sm.red[14];
            out[3 * N + r] = sm.red[3] * sm.red[7] * sm.red[11] * sm.red[15];
        }
    }
}

// ---------------------------------------------------------------------------
extern "C" void kernel_launch(void* const* d_in, const int* in_sizes, int n_in,
                              void* d_out, int out_size) {
    const float* orig = (const float*)d_in[0];
    const float* dirs = (const float*)d_in[1];
    const float* tmin = (const float*)d_in[2];
    const float* tmax = (const float*)d_in[3];
    const float* W1   = (const float*)d_in[4];
    const float* b1   = (const float*)d_in[5];
    const float* W2   = (const float*)d_in[6];
    const float* b2   = (const float*)d_in[7];
    const float* V1   = (const float*)d_in[8];
    const float* c1   = (const float*)d_in[9];
    const float* V2   = (const float*)d_in[10];
    const float* c2   = (const float*)d_in[11];
    float* out = (float*)d_out;
    const int N = in_sizes[2];

    const int smem_bytes = (int)sizeof(SmemT);
    cudaFuncSetAttribute(raymarch_kernel,
                         cudaFuncAttributeMaxDynamicSharedMemorySize, smem_bytes);

    reduce_dt_kernel<<<1, 256>>>(tmin, tmax, N);
    raymarch_kernel<<<N, SS, smem_bytes>>>(orig, dirs, tmin, tmax, W1, b1, W2, b2,
                                           V1, c1, V2, c2, out, N);
}

// round 5
// speedup vs baseline: 1.2044x; 1.0965x over previous
#include <cuda_runtime.h>
#include <math.h>

#define SS 128
#define POS_BANDS 10
#define D_ENC 63
#define D_VD 27
#define HID 64
#define FEAT 15

__device__ float g_dt;

// ---------------- packed f32x2 FMA ----------------
struct F2 { union { float2 f; unsigned long long u; }; };
__device__ __forceinline__ F2 f2mk(float x, float y) { F2 r; r.f.x = x; r.f.y = y; return r; }
__device__ __forceinline__ F2 f2dup(float x) { return f2mk(x, x); }
__device__ __forceinline__ void fma2(F2& d, const F2 a, const F2 b) {
    asm("fma.rn.f32x2 %0, %1, %2, %0;" : "+l"(d.u) : "l"(a.u), "l"(b.u));
}

// ---------------------------------------------------------------------------
__global__ void reduce_dt_kernel(const float* __restrict__ tmin,
                                 const float* __restrict__ tmax, int n) {
    __shared__ float sh[256];
    float s = 0.f;
    for (int i = threadIdx.x; i < n; i += 256) s += tmax[i] - tmin[i];
    sh[threadIdx.x] = s;
    __syncthreads();
    for (int o = 128; o > 0; o >>= 1) {
        if (threadIdx.x < o) sh[threadIdx.x] += sh[threadIdx.x + o];
        __syncthreads();
    }
    if (threadIdx.x == 0) g_dt = sh[0] / (float)n / (float)SS;
}

// ---------------------------------------------------------------------------
// bufA is reused three times: ENC^T (63 rows) -> H^T (64 rows) -> G^T (64 rows)
struct __align__(16) SmemT {
    float bufA[64 * SS];   // 32 KB
    float Ot[16 * SS];     // 8 KB   O^T (row 0 = raw sigma pre-relu)
    float W1s[64 * 64];    // 16 KB  rows 0..62 used, [k][j]
    float W2s[64 * 16];    // 4 KB
    float V1s[16 * 64];    // 4 KB   rows 0..14
    float V2p[64 * 4];     // 1 KB
    float b1s[64];
    float b2s[16];
    float basev[64];
    float c2s[4];
    float vd[28];
    float wagg[4];
    float red[16];
};

__global__ void __launch_bounds__(SS, 3)
raymarch_kernel(const float* __restrict__ orig, const float* __restrict__ dirs,
                const float* __restrict__ tmin, const float* __restrict__ tmax,
                const float* __restrict__ W1, const float* __restrict__ b1,
                const float* __restrict__ W2, const float* __restrict__ b2,
                const float* __restrict__ V1, const float* __restrict__ c1,
                const float* __restrict__ V2, const float* __restrict__ c2,
                float* __restrict__ out, int N) {
    extern __shared__ char smem_raw[];
    SmemT& sm = *reinterpret_cast<SmemT*>(smem_raw);
    const int r = blockIdx.x;
    const int tid = threadIdx.x;
    const int lane = tid & 31;
    const int warp = tid >> 5;

    // ---- stage weights ----
    for (int i = tid; i < D_ENC * HID; i += SS) sm.W1s[i] = W1[i];
    for (int i = tid; i < HID * 16; i += SS) sm.W2s[i] = W2[i];
    for (int i = tid; i < FEAT * HID; i += SS) sm.V1s[i] = V1[i];
    if (tid < HID) {
        sm.b1s[tid] = b1[tid];
        sm.V2p[tid * 4 + 0] = V2[tid * 3 + 0];
        sm.V2p[tid * 4 + 1] = V2[tid * 3 + 1];
        sm.V2p[tid * 4 + 2] = V2[tid * 3 + 2];
        sm.V2p[tid * 4 + 3] = 0.f;
    }
    if (tid < 16) sm.b2s[tid] = b2[tid];
    if (tid < 4) sm.c2s[tid] = (tid < 3) ? c2[tid] : 0.f;

    const float dx = dirs[r * 3 + 0], dy = dirs[r * 3 + 1], dz = dirs[r * 3 + 2];
    const float inv = 1.f / (sqrtf(dx * dx + dy * dy + dz * dz) + 1e-8f);
    if (tid < D_VD) {
        const int p = tid / 3, c = tid % 3;
        float v = ((c == 0) ? dx : (c == 1) ? dy : dz) * inv;
        float val;
        if (p == 0) val = v;
        else {
            const int band = (p - 1) >> 1;
            float sn, cs;
            sincosf(v * (float)(1 << band), &sn, &cs);
            val = ((p - 1) & 1) ? cs : sn;
        }
        sm.vd[tid] = val;
    }
    __syncthreads();

    // ---- base = c1 + vd_enc @ V1[15:42]  (per-ray constant) ----
    if (tid < HID) {
        float acc = c1[tid];
#pragma unroll
        for (int k = 0; k < D_VD; k++) acc += sm.vd[k] * V1[(FEAT + k) * HID + tid];
        sm.basev[tid] = acc;
    }

    // ---- positional encoding -> ENC^T in bufA rows 0..62 ----
    {
        const float t0 = tmin[r], t1 = tmax[r];
        const float tt = t0 + (float)tid * (1.f / (SS - 1)) * (t1 - t0);
        const float px = orig[r * 3 + 0] + dx * tt;
        const float py = orig[r * 3 + 1] + dy * tt;
        const float pz = orig[r * 3 + 2] + dz * tt;
        sm.bufA[0 * SS + tid] = px;
        sm.bufA[1 * SS + tid] = py;
        sm.bufA[2 * SS + tid] = pz;
#pragma unroll
        for (int b = 0; b < POS_BANDS; b++) {
            const float f = (float)(1 << b);
            float sn, cs;
            sincosf(f * px, &sn, &cs);
            sm.bufA[(3 + 6 * b + 0) * SS + tid] = sn;
            sm.bufA[(6 + 6 * b + 0) * SS + tid] = cs;
            sincosf(f * py, &sn, &cs);
            sm.bufA[(3 + 6 * b + 1) * SS + tid] = sn;
            sm.bufA[(6 + 6 * b + 1) * SS + tid] = cs;
            sincosf(f * pz, &sn, &cs);
            sm.bufA[(3 + 6 * b + 2) * SS + tid] = sn;
            sm.bufA[(6 + 6 * b + 2) * SS + tid] = cs;
        }
    }
    __syncthreads();

    // ======== Layer 1: H^T = relu(W1^T @ ENC)  [64 x 128] ========
    {
        const int cg = tid & 7, rg = tid >> 3;
        const int col0 = cg * 8, s0 = rg * 8;
        F2 acc[4][8];
#pragma unroll
        for (int j = 0; j < 8; j++) {
            const F2 bb = f2dup(sm.b1s[col0 + j]);
#pragma unroll
            for (int p = 0; p < 4; p++) acc[p][j] = bb;
        }
        // prefetch distance-1 pipeline
        float4 a0 = *(const float4*)&sm.bufA[0 * SS + s0];
        float4 a1 = *(const float4*)&sm.bufA[0 * SS + s0 + 4];
        float4 w0 = *(const float4*)&sm.W1s[0 * HID + col0];
        float4 w1 = *(const float4*)&sm.W1s[0 * HID + col0 + 4];
#pragma unroll 2
        for (int k = 0; k < D_ENC - 1; k++) {
            const float4 na0 = *(const float4*)&sm.bufA[(k + 1) * SS + s0];
            const float4 na1 = *(const float4*)&sm.bufA[(k + 1) * SS + s0 + 4];
            const float4 nw0 = *(const float4*)&sm.W1s[(k + 1) * HID + col0];
            const float4 nw1 = *(const float4*)&sm.W1s[(k + 1) * HID + col0 + 4];
            F2 a[4] = {f2mk(a0.x, a0.y), f2mk(a0.z, a0.w), f2mk(a1.x, a1.y), f2mk(a1.z, a1.w)};
            const float wv[8] = {w0.x, w0.y, w0.z, w0.w, w1.x, w1.y, w1.z, w1.w};
#pragma unroll
            for (int j = 0; j < 8; j++) {
                const F2 bw = f2dup(wv[j]);
#pragma unroll
                for (int p = 0; p < 4; p++) fma2(acc[p][j], a[p], bw);
            }
            a0 = na0; a1 = na1; w0 = nw0; w1 = nw1;
        }
        {
            F2 a[4] = {f2mk(a0.x, a0.y), f2mk(a0.z, a0.w), f2mk(a1.x, a1.y), f2mk(a1.z, a1.w)};
            const float wv[8] = {w0.x, w0.y, w0.z, w0.w, w1.x, w1.y, w1.z, w1.w};
#pragma unroll
            for (int j = 0; j < 8; j++) {
                const F2 bw = f2dup(wv[j]);
#pragma unroll
                for (int p = 0; p < 4; p++) fma2(acc[p][j], a[p], bw);
            }
        }
        __syncthreads();   // all ENC reads done before overwriting bufA
#pragma unroll
        for (int j = 0; j < 8; j++)
#pragma unroll
            for (int p = 0; p < 4; p++) {
                float2 v = acc[p][j].f;
                v.x = fmaxf(v.x, 0.f);
                v.y = fmaxf(v.y, 0.f);
                *(float2*)&sm.bufA[(col0 + j) * SS + s0 + 2 * p] = v;
            }
    }
    __syncthreads();

    // ======== Layer 2: O^T = W2^T @ H  [16 x 128] ========
    {
        const int cg = tid & 3, rg = tid >> 2;
        const int col0 = cg * 4, s0 = rg * 4;
        F2 acc[2][4];
#pragma unroll
        for (int j = 0; j < 4; j++) {
            const F2 bb = f2dup(sm.b2s[col0 + j]);
            acc[0][j] = bb; acc[1][j] = bb;
        }
#pragma unroll 4
        for (int k = 0; k < HID; k++) {
            const float4 a0 = *(const float4*)&sm.bufA[k * SS + s0];
            const float4 w0 = *(const float4*)&sm.W2s[k * 16 + col0];
            F2 a[2] = {f2mk(a0.x, a0.y), f2mk(a0.z, a0.w)};
            const float wv[4] = {w0.x, w0.y, w0.z, w0.w};
#pragma unroll
            for (int j = 0; j < 4; j++) {
                const F2 bw = f2dup(wv[j]);
                fma2(acc[0][j], a[0], bw);
                fma2(acc[1][j], a[1], bw);
            }
        }
#pragma unroll
        for (int j = 0; j < 4; j++) {
            *(float2*)&sm.Ot[(col0 + j) * SS + s0] = acc[0][j].f;
            *(float2*)&sm.Ot[(col0 + j) * SS + s0 + 2] = acc[1][j].f;
        }
    }
    __syncthreads();   // Ot visible; all H reads done

    // ======== Layer 3: G^T = relu(base + V1a^T @ rgb_feat)  [64 x 128] ========
    {
        const int cg = tid & 7, rg = tid >> 3;
        const int col0 = cg * 8, s0 = rg * 8;
        F2 acc[4][8];
#pragma unroll
        for (int j = 0; j < 8; j++) {
            const F2 bb = f2dup(sm.basev[col0 + j]);
#pragma unroll
            for (int p = 0; p < 4; p++) acc[p][j] = bb;
        }
#pragma unroll
        for (int k = 0; k < FEAT; k++) {
            const float4 a0 = *(const float4*)&sm.Ot[(k + 1) * SS + s0];
            const float4 a1 = *(const float4*)&sm.Ot[(k + 1) * SS + s0 + 4];
            const float4 w0 = *(const float4*)&sm.V1s[k * HID + col0];
            const float4 w1 = *(const float4*)&sm.V1s[k * HID + col0 + 4];
            F2 a[4] = {f2mk(a0.x, a0.y), f2mk(a0.z, a0.w), f2mk(a1.x, a1.y), f2mk(a1.z, a1.w)};
            const float wv[8] = {w0.x, w0.y, w0.z, w0.w, w1.x, w1.y, w1.z, w1.w};
#pragma unroll
            for (int j = 0; j < 8; j++) {
                const F2 bw = f2dup(wv[j]);
#pragma unroll
                for (int p = 0; p < 4; p++) fma2(acc[p][j], a[p], bw);
            }
        }
        // bufA(H) fully consumed at the last barrier; safe to overwrite with G
#pragma unroll
        for (int j = 0; j < 8; j++)
#pragma unroll
            for (int p = 0; p < 4; p++) {
                float2 v = acc[p][j].f;
                v.x = fmaxf(v.x, 0.f);
                v.y = fmaxf(v.y, 0.f);
                *(float2*)&sm.bufA[(col0 + j) * SS + s0 + 2 * p] = v;
            }
    }
    __syncthreads();

    // ======== Layer 4 + compositing (per-sample) ========
    {
        const int s = tid;
        float r0 = sm.c2s[0], r1 = sm.c2s[1], r2 = sm.c2s[2];
#pragma unroll 8
        for (int k = 0; k < HID; k++) {
            const float g = sm.bufA[k * SS + s];
            const float4 w = *(const float4*)&sm.V2p[k * 4];
            r0 += g * w.x;
            r1 += g * w.y;
            r2 += g * w.z;
        }
        r0 = 1.f / (1.f + expf(-r0));
        r1 = 1.f / (1.f + expf(-r1));
        r2 = 1.f / (1.f + expf(-r2));

        const float sigma = fmaxf(sm.Ot[s], 0.f);
        const float dtv = g_dt;
        const float om = expf(-sigma * dtv);
        const float alpha = 1.f - om;

        // ---- warp-level exclusive product scan ----
        float e = __shfl_up_sync(0xffffffffu, om, 1);
        if (lane == 0) e = 1.f;
        float x = e;
#pragma unroll
        for (int off = 1; off < 32; off <<= 1) {
            const float v = __shfl_up_sync(0xffffffffu, x, off);
            if (lane >= off) x *= v;
        }
        // x = Prod_{i<lane} om_i (within warp). Warp total:
        if (lane == 31) sm.wagg[warp] = x * om;
        __syncthreads();
        float pre = 1.f;
#pragma unroll
        for (int w2 = 0; w2 < 4; w2++)
            if (w2 < warp) pre *= sm.wagg[w2];
        const float Texcl = pre * x;

        const bool active = (Texcl > 1e-4f);
        const float w = active ? Texcl * alpha : 0.f;

        float cr = w * r0, cg2 = w * r1, cb = w * r2;
        float tf = active ? om : 1.f;
#pragma unroll
        for (int off = 16; off; off >>= 1) {
            cr  += __shfl_down_sync(0xffffffffu, cr,  off);
            cg2 += __shfl_down_sync(0xffffffffu, cg2, off);
            cb  += __shfl_down_sync(0xffffffffu, cb,  off);
            tf  *= __shfl_down_sync(0xffffffffu, tf,  off);
        }
        if (lane == 0) {
            sm.red[warp * 4 + 0] = cr;
            sm.red[warp * 4 + 1] = cg2;
            sm.red[warp * 4 + 2] = cb;
            sm.red[warp * 4 + 3] = tf;
        }
        __syncthreads();
        if (s == 0) {
            out[r * 3 + 0] = sm.red[0] + sm.red[4] + sm.red[8] + sm.red[12];
            out[r * 3 + 1] = sm.red[1] + sm.red[5] + sm.red[9] + sm.red[13];
            out[r * 3 + 2] = sm.red[2] + sm.red[6] + sm.red[10] + sm.red[14];
            out[3 * N + r] = sm.red[3] * sm.red[7] * sm.red[11] * sm.red[15];
        }
    }
}

// ---------------------------------------------------------------------------
extern "C" void kernel_launch(void* const* d_in, const int* in_sizes, int n_in,
                              void* d_out, int out_size) {
    const float* orig = (const float*)d_in[0];
    const float* dirs = (const float*)d_in[1];
    const float* tmin = (const float*)d_in[2];
    const float* tmax = (const float*)d_in[3];
    const float* W1   = (const float*)d_in[4];
    const float* b1   = (const float*)d_in[5];
    const float* W2   = (const float*)d_in[6];
    const float* b2   = (const float*)d_in[7];
    const float* V1   = (const float*)d_in[8];
    const float* c1   = (const float*)d_in[9];
    const float* V2   = (const float*)d_in[10];
    const float* c2   = (const float*)d_in[11];
    float* out = (float*)d_out;
    const int N = in_sizes[2];

    const int smem_bytes = (int)sizeof(SmemT);
    cudaFuncSetAttribute(raymarch_kernel,
                         cudaFuncAttributeMaxDynamicSharedMemorySize, smem_bytes);

    reduce_dt_kernel<<<1, 256>>>(tmin, tmax, N);
    raymarch_kernel<<<N, SS, smem_bytes>>>(orig, dirs, tmin, tmax, W1, b1, W2, b2,
                                           V1, c1, V2, c2, out, N);
}

// round 6
// speedup vs baseline: 1.4630x; 1.2147x over previous
#include <cuda_runtime.h>
#include <math.h>

#define SS 128
#define POS_BANDS 10
#define D_ENC 63
#define D_VD 27
#define HID 64
#define FEAT 15

__device__ float g_dt;

// ---- weights in constant memory (uniform-const port, off the L1tex path) ----
__constant__ float W1c[D_ENC * HID];   // 16128 B
__constant__ float b1c[HID];
__constant__ float W2c[HID * 16];
__constant__ float b2c[16];
__constant__ float V1c[FEAT * HID];    // rows 0..14 only
__constant__ float V2c[HID * 3];
__constant__ float c2c[3];

// ---------------- packed f32x2 FMA ----------------
struct F2 { union { float2 f; unsigned long long u; }; };
__device__ __forceinline__ F2 f2mk(float x, float y) { F2 r; r.f.x = x; r.f.y = y; return r; }
__device__ __forceinline__ F2 f2dup(float x) { return f2mk(x, x); }
__device__ __forceinline__ void fma2(F2& d, const F2 a, const F2 b) {
    asm("fma.rn.f32x2 %0, %1, %2, %0;" : "+l"(d.u) : "l"(a.u), "l"(b.u));
}

// ---------------------------------------------------------------------------
__global__ void reduce_dt_kernel(const float* __restrict__ tmin,
                                 const float* __restrict__ tmax, int n) {
    __shared__ float sh[256];
    float s = 0.f;
    for (int i = threadIdx.x; i < n; i += 256) s += tmax[i] - tmin[i];
    sh[threadIdx.x] = s;
    __syncthreads();
    for (int o = 128; o > 0; o >>= 1) {
        if (threadIdx.x < o) sh[threadIdx.x] += sh[threadIdx.x + o];
        __syncthreads();
    }
    if (threadIdx.x == 0) g_dt = sh[0] / (float)n / (float)SS;
}

// ---------------------------------------------------------------------------
struct __align__(16) SmemT {
    float bufA[64 * SS];   // 32 KB: ENC^T -> H^T -> G^T
    float Ot[16 * SS];     // 8 KB:  O^T (row 0 = raw sigma pre-relu)
    float basev[64];       // c1 + vd_enc @ V1[15:42]
    float vd[28];
    float wagg[4];
    float red[16];
};

__global__ void __launch_bounds__(SS, 4)
raymarch_kernel(const float* __restrict__ orig, const float* __restrict__ dirs,
                const float* __restrict__ tmin, const float* __restrict__ tmax,
                const float* __restrict__ V1, const float* __restrict__ c1,
                float* __restrict__ out, int N) {
    extern __shared__ char smem_raw[];
    SmemT& sm = *reinterpret_cast<SmemT*>(smem_raw);
    const int r = blockIdx.x;
    const int tid = threadIdx.x;
    const int lane = tid & 31;
    const int warp = tid >> 5;
    const int s0 = lane * 4;        // 4 samples per lane (GEMM tiles)
    const int col0 = warp * 16;     // 16 output columns per warp (uniform)

    const float dx = dirs[r * 3 + 0], dy = dirs[r * 3 + 1], dz = dirs[r * 3 + 2];
    const float inv = 1.f / (sqrtf(dx * dx + dy * dy + dz * dz) + 1e-8f);
    if (tid < D_VD) {
        const int p = tid / 3, c = tid % 3;
        float v = ((c == 0) ? dx : (c == 1) ? dy : dz) * inv;
        float val;
        if (p == 0) val = v;
        else {
            const int band = (p - 1) >> 1;
            float sn, cs;
            sincosf(v * (float)(1 << band), &sn, &cs);
            val = ((p - 1) & 1) ? cs : sn;
        }
        sm.vd[tid] = val;
    }
    __syncthreads();

    // ---- base = c1 + vd_enc @ V1[15:42]  (per-ray constant; coalesced LDG) ----
    if (tid < HID) {
        float acc = c1[tid];
#pragma unroll
        for (int k = 0; k < D_VD; k++) acc += sm.vd[k] * V1[(FEAT + k) * HID + tid];
        sm.basev[tid] = acc;
    }

    // ---- positional encoding -> ENC^T in bufA rows 0..62 ----
    {
        const float t0 = tmin[r], t1 = tmax[r];
        const float tt = t0 + (float)tid * (1.f / (SS - 1)) * (t1 - t0);
        const float px = orig[r * 3 + 0] + dx * tt;
        const float py = orig[r * 3 + 1] + dy * tt;
        const float pz = orig[r * 3 + 2] + dz * tt;
        sm.bufA[0 * SS + tid] = px;
        sm.bufA[1 * SS + tid] = py;
        sm.bufA[2 * SS + tid] = pz;
#pragma unroll
        for (int b = 0; b < POS_BANDS; b++) {
            const float f = (float)(1 << b);
            float sn, cs;
            sincosf(f * px, &sn, &cs);
            sm.bufA[(3 + 6 * b + 0) * SS + tid] = sn;
            sm.bufA[(6 + 6 * b + 0) * SS + tid] = cs;
            sincosf(f * py, &sn, &cs);
            sm.bufA[(3 + 6 * b + 1) * SS + tid] = sn;
            sm.bufA[(6 + 6 * b + 1) * SS + tid] = cs;
            sincosf(f * pz, &sn, &cs);
            sm.bufA[(3 + 6 * b + 2) * SS + tid] = sn;
            sm.bufA[(6 + 6 * b + 2) * SS + tid] = cs;
        }
    }
    __syncthreads();

    // ======== Layer 1: H^T = relu(W1^T @ ENC), warp-uniform weights ========
    {
        F2 acc[4][8];   // [sample][colpair]
#pragma unroll
        for (int cp = 0; cp < 8; cp++) {
            const F2 bb = f2mk(b1c[col0 + 2 * cp], b1c[col0 + 2 * cp + 1]);
#pragma unroll
            for (int s = 0; s < 4; s++) acc[s][cp] = bb;
        }
#pragma unroll 7
        for (int k = 0; k < D_ENC; k++) {
            const float4 av = *(const float4*)&sm.bufA[k * SS + s0];
            const float4 w0 = *(const float4*)&W1c[k * HID + col0];
            const float4 w1 = *(const float4*)&W1c[k * HID + col0 + 4];
            const float4 w2 = *(const float4*)&W1c[k * HID + col0 + 8];
            const float4 w3 = *(const float4*)&W1c[k * HID + col0 + 12];
            const F2 wp[8] = {f2mk(w0.x, w0.y), f2mk(w0.z, w0.w),
                              f2mk(w1.x, w1.y), f2mk(w1.z, w1.w),
                              f2mk(w2.x, w2.y), f2mk(w2.z, w2.w),
                              f2mk(w3.x, w3.y), f2mk(w3.z, w3.w)};
            const float as[4] = {av.x, av.y, av.z, av.w};
#pragma unroll
            for (int s = 0; s < 4; s++) {
                const F2 ad = f2dup(as[s]);
#pragma unroll
                for (int cp = 0; cp < 8; cp++) fma2(acc[s][cp], ad, wp[cp]);
            }
        }
        __syncthreads();   // all ENC reads done before overwriting bufA
#pragma unroll
        for (int cp = 0; cp < 8; cp++) {
            float4 v0, v1;
            v0.x = fmaxf(acc[0][cp].f.x, 0.f); v1.x = fmaxf(acc[0][cp].f.y, 0.f);
            v0.y = fmaxf(acc[1][cp].f.x, 0.f); v1.y = fmaxf(acc[1][cp].f.y, 0.f);
            v0.z = fmaxf(acc[2][cp].f.x, 0.f); v1.z = fmaxf(acc[2][cp].f.y, 0.f);
            v0.w = fmaxf(acc[3][cp].f.x, 0.f); v1.w = fmaxf(acc[3][cp].f.y, 0.f);
            *(float4*)&sm.bufA[(col0 + 2 * cp) * SS + s0] = v0;
            *(float4*)&sm.bufA[(col0 + 2 * cp + 1) * SS + s0] = v1;
        }
    }
    __syncthreads();

    // ======== Layer 2: O^T = W2^T @ H, one sample per thread ========
    {
        F2 o2[8];
#pragma unroll
        for (int cp = 0; cp < 8; cp++) o2[cp] = f2mk(b2c[2 * cp], b2c[2 * cp + 1]);
#pragma unroll 8
        for (int k = 0; k < HID; k++) {
            const float h = sm.bufA[k * SS + tid];
            const F2 hd = f2dup(h);
            const float4 w0 = *(const float4*)&W2c[k * 16 + 0];
            const float4 w1 = *(const float4*)&W2c[k * 16 + 4];
            const float4 w2 = *(const float4*)&W2c[k * 16 + 8];
            const float4 w3 = *(const float4*)&W2c[k * 16 + 12];
            const F2 wp[8] = {f2mk(w0.x, w0.y), f2mk(w0.z, w0.w),
                              f2mk(w1.x, w1.y), f2mk(w1.z, w1.w),
                              f2mk(w2.x, w2.y), f2mk(w2.z, w2.w),
                              f2mk(w3.x, w3.y), f2mk(w3.z, w3.w)};
#pragma unroll
            for (int cp = 0; cp < 8; cp++) fma2(o2[cp], hd, wp[cp]);
        }
#pragma unroll
        for (int cp = 0; cp < 8; cp++) {
            sm.Ot[(2 * cp) * SS + tid] = o2[cp].f.x;
            sm.Ot[(2 * cp + 1) * SS + tid] = o2[cp].f.y;
        }
    }
    __syncthreads();   // Ot visible; all H reads done

    // ======== Layer 3: G^T = relu(base + V1a^T @ rgb_feat) ========
    {
        F2 acc[4][8];
#pragma unroll
        for (int cp = 0; cp < 8; cp++) {
            const F2 bb = f2mk(sm.basev[col0 + 2 * cp], sm.basev[col0 + 2 * cp + 1]);
#pragma unroll
            for (int s = 0; s < 4; s++) acc[s][cp] = bb;
        }
#pragma unroll
        for (int k = 0; k < FEAT; k++) {
            const float4 av = *(const float4*)&sm.Ot[(k + 1) * SS + s0];
            const float4 w0 = *(const float4*)&V1c[k * HID + col0];
            const float4 w1 = *(const float4*)&V1c[k * HID + col0 + 4];
            const float4 w2 = *(const float4*)&V1c[k * HID + col0 + 8];
            const float4 w3 = *(const float4*)&V1c[k * HID + col0 + 12];
            const F2 wp[8] = {f2mk(w0.x, w0.y), f2mk(w0.z, w0.w),
                              f2mk(w1.x, w1.y), f2mk(w1.z, w1.w),
                              f2mk(w2.x, w2.y), f2mk(w2.z, w2.w),
                              f2mk(w3.x, w3.y), f2mk(w3.z, w3.w)};
            const float as[4] = {av.x, av.y, av.z, av.w};
#pragma unroll
            for (int s = 0; s < 4; s++) {
                const F2 ad = f2dup(as[s]);
#pragma unroll
                for (int cp = 0; cp < 8; cp++) fma2(acc[s][cp], ad, wp[cp]);
            }
        }
        // H fully consumed at post-layer2 barrier; safe to overwrite bufA
#pragma unroll
        for (int cp = 0; cp < 8; cp++) {
            float4 v0, v1;
            v0.x = fmaxf(acc[0][cp].f.x, 0.f); v1.x = fmaxf(acc[0][cp].f.y, 0.f);
            v0.y = fmaxf(acc[1][cp].f.x, 0.f); v1.y = fmaxf(acc[1][cp].f.y, 0.f);
            v0.z = fmaxf(acc[2][cp].f.x, 0.f); v1.z = fmaxf(acc[2][cp].f.y, 0.f);
            v0.w = fmaxf(acc[3][cp].f.x, 0.f); v1.w = fmaxf(acc[3][cp].f.y, 0.f);
            *(float4*)&sm.bufA[(col0 + 2 * cp) * SS + s0] = v0;
            *(float4*)&sm.bufA[(col0 + 2 * cp + 1) * SS + s0] = v1;
        }
    }
    __syncthreads();

    // ======== Layer 4 + compositing (per-sample) ========
    {
        const int s = tid;
        float r0 = c2c[0], r1 = c2c[1], r2 = c2c[2];
#pragma unroll 8
        for (int k = 0; k < HID; k++) {
            const float g = sm.bufA[k * SS + s];
            r0 += g * V2c[k * 3 + 0];
            r1 += g * V2c[k * 3 + 1];
            r2 += g * V2c[k * 3 + 2];
        }
        r0 = 1.f / (1.f + expf(-r0));
        r1 = 1.f / (1.f + expf(-r1));
        r2 = 1.f / (1.f + expf(-r2));

        const float sigma = fmaxf(sm.Ot[s], 0.f);
        const float dtv = g_dt;
        const float om = expf(-sigma * dtv);
        const float alpha = 1.f - om;

        // ---- warp-level exclusive product scan ----
        float e = __shfl_up_sync(0xffffffffu, om, 1);
        if (lane == 0) e = 1.f;
        float x = e;
#pragma unroll
        for (int off = 1; off < 32; off <<= 1) {
            const float v = __shfl_up_sync(0xffffffffu, x, off);
            if (lane >= off) x *= v;
        }
        if (lane == 31) sm.wagg[warp] = x * om;
        __syncthreads();
        float pre = 1.f;
#pragma unroll
        for (int w2 = 0; w2 < 4; w2++)
            if (w2 < warp) pre *= sm.wagg[w2];
        const float Texcl = pre * x;

        const bool active = (Texcl > 1e-4f);
        const float w = active ? Texcl * alpha : 0.f;

        float cr = w * r0, cg2 = w * r1, cb = w * r2;
        float tf = active ? om : 1.f;
#pragma unroll
        for (int off = 16; off; off >>= 1) {
            cr  += __shfl_down_sync(0xffffffffu, cr,  off);
            cg2 += __shfl_down_sync(0xffffffffu, cg2, off);
            cb  += __shfl_down_sync(0xffffffffu, cb,  off);
            tf  *= __shfl_down_sync(0xffffffffu, tf,  off);
        }
        if (lane == 0) {
            sm.red[warp * 4 + 0] = cr;
            sm.red[warp * 4 + 1] = cg2;
            sm.red[warp * 4 + 2] = cb;
            sm.red[warp * 4 + 3] = tf;
        }
        __syncthreads();
        if (s == 0) {
            out[r * 3 + 0] = sm.red[0] + sm.red[4] + sm.red[8] + sm.red[12];
            out[r * 3 + 1] = sm.red[1] + sm.red[5] + sm.red[9] + sm.red[13];
            out[r * 3 + 2] = sm.red[2] + sm.red[6] + sm.red[10] + sm.red[14];
            out[3 * N + r] = sm.red[3] * sm.red[7] * sm.red[11] * sm.red[15];
        }
    }
}

// ---------------------------------------------------------------------------
extern "C" void kernel_launch(void* const* d_in, const int* in_sizes, int n_in,
                              void* d_out, int out_size) {
    const float* orig = (const float*)d_in[0];
    const float* dirs = (const float*)d_in[1];
    const float* tmin = (const float*)d_in[2];
    const float* tmax = (const float*)d_in[3];
    const float* W1   = (const float*)d_in[4];
    const float* b1   = (const float*)d_in[5];
    const float* W2   = (const float*)d_in[6];
    const float* b2   = (const float*)d_in[7];
    const float* V1   = (const float*)d_in[8];
    const float* c1   = (const float*)d_in[9];
    const float* V2   = (const float*)d_in[10];
    const float* c2   = (const float*)d_in[11];
    float* out = (float*)d_out;
    const int N = in_sizes[2];

    // stage weights into constant memory (device-to-device, capture-safe)
    cudaMemcpyToSymbolAsync(W1c, W1, D_ENC * HID * sizeof(float), 0, cudaMemcpyDeviceToDevice, 0);
    cudaMemcpyToSymbolAsync(b1c, b1, HID * sizeof(float), 0, cudaMemcpyDeviceToDevice, 0);
    cudaMemcpyToSymbolAsync(W2c, W2, HID * 16 * sizeof(float), 0, cudaMemcpyDeviceToDevice, 0);
    cudaMemcpyToSymbolAsync(b2c, b2, 16 * sizeof(float), 0, cudaMemcpyDeviceToDevice, 0);
    cudaMemcpyToSymbolAsync(V1c, V1, FEAT * HID * sizeof(float), 0, cudaMemcpyDeviceToDevice, 0);
    cudaMemcpyToSymbolAsync(V2c, V2, HID * 3 * sizeof(float), 0, cudaMemcpyDeviceToDevice, 0);
    cudaMemcpyToSymbolAsync(c2c, c2, 3 * sizeof(float), 0, cudaMemcpyDeviceToDevice, 0);

    reduce_dt_kernel<<<1, 256>>>(tmin, tmax, N);
    raymarch_kernel<<<N, SS, sizeof(SmemT)>>>(orig, dirs, tmin, tmax,
                                              V1, c1, out, N);
}

// round 7
// speedup vs baseline: 1.5684x; 1.0721x over previous
#include <cuda_runtime.h>
#include <math.h>

#define SS 128
#define POS_BANDS 10
#define D_ENC 63
#define D_VD 27
#define HID 64
#define FEAT 15

__device__ float g_dt;

// ---- weights in constant memory (uniform-const port, off the L1tex path) ----
__constant__ float W1c[D_ENC * HID];
__constant__ float b1c[HID];
__constant__ float W2c[HID * 16];
__constant__ float b2c[16];
__constant__ float V1c[FEAT * HID];    // rows 0..14 only
__constant__ float V2c[HID * 3];
__constant__ float c2c[3];

// ---------------- packed f32x2 FMA ----------------
struct F2 { union { float2 f; unsigned long long u; }; };
__device__ __forceinline__ F2 f2mk(float x, float y) { F2 r; r.f.x = x; r.f.y = y; return r; }
__device__ __forceinline__ F2 f2dup(float x) { return f2mk(x, x); }
__device__ __forceinline__ void fma2(F2& d, const F2 a, const F2 b) {
    asm("fma.rn.f32x2 %0, %1, %2, %0;" : "+l"(d.u) : "l"(a.u), "l"(b.u));
}

// ---------------------------------------------------------------------------
__global__ void reduce_dt_kernel(const float* __restrict__ tmin,
                                 const float* __restrict__ tmax, int n) {
    __shared__ float sh[256];
    float s = 0.f;
    for (int i = threadIdx.x; i < n; i += 256) s += tmax[i] - tmin[i];
    sh[threadIdx.x] = s;
    __syncthreads();
    for (int o = 128; o > 0; o >>= 1) {
        if (threadIdx.x < o) sh[threadIdx.x] += sh[threadIdx.x + o];
        __syncthreads();
    }
    if (threadIdx.x == 0) g_dt = sh[0] / (float)n / (float)SS;
}

// ---------------------------------------------------------------------------
struct __align__(16) SmemT {
    float bufA[64 * SS];   // 32 KB: ENC^T (rows 0..62) -> H^T (rows 0..63)
    float basev[64];       // c1 + vd_enc @ V1[15:42]
    float vd[28];
    float wagg[4];
    float red[16];
};

__global__ void __launch_bounds__(SS, 4)
raymarch_kernel(const float* __restrict__ orig, const float* __restrict__ dirs,
                const float* __restrict__ tmin, const float* __restrict__ tmax,
                const float* __restrict__ V1, const float* __restrict__ c1,
                float* __restrict__ out, int N) {
    extern __shared__ char smem_raw[];
    SmemT& sm = *reinterpret_cast<SmemT*>(smem_raw);
    const int r = blockIdx.x;
    const int tid = threadIdx.x;
    const int lane = tid & 31;
    const int warp = tid >> 5;
    const int s0 = lane * 4;        // layer-1 tile: 4 samples per lane
    const int col0 = warp * 16;     // layer-1 tile: 16 columns per warp (uniform)

    const float dx = dirs[r * 3 + 0], dy = dirs[r * 3 + 1], dz = dirs[r * 3 + 2];
    const float inv = 1.f / (sqrtf(dx * dx + dy * dy + dz * dz) + 1e-8f);
    if (tid < D_VD) {
        const int p = tid / 3, c = tid % 3;
        float v = ((c == 0) ? dx : (c == 1) ? dy : dz) * inv;
        float val;
        if (p == 0) val = v;
        else {
            const int band = (p - 1) >> 1;
            float sn, cs;
            sincosf(v * (float)(1 << band), &sn, &cs);
            val = ((p - 1) & 1) ? cs : sn;
        }
        sm.vd[tid] = val;
    }
    __syncthreads();

    // ---- base = c1 + vd_enc @ V1[15:42]  (per-ray constant; coalesced LDG) ----
    if (tid < HID) {
        float acc = c1[tid];
#pragma unroll
        for (int k = 0; k < D_VD; k++) acc += sm.vd[k] * V1[(FEAT + k) * HID + tid];
        sm.basev[tid] = acc;
    }

    // ---- positional encoding -> ENC^T in bufA rows 0..62 ----
    {
        const float t0 = tmin[r], t1 = tmax[r];
        const float tt = t0 + (float)tid * (1.f / (SS - 1)) * (t1 - t0);
        const float px = orig[r * 3 + 0] + dx * tt;
        const float py = orig[r * 3 + 1] + dy * tt;
        const float pz = orig[r * 3 + 2] + dz * tt;
        sm.bufA[0 * SS + tid] = px;
        sm.bufA[1 * SS + tid] = py;
        sm.bufA[2 * SS + tid] = pz;
#pragma unroll
        for (int b = 0; b < POS_BANDS; b++) {
            const float f = (float)(1 << b);
            float sn, cs;
            sincosf(f * px, &sn, &cs);
            sm.bufA[(3 + 6 * b + 0) * SS + tid] = sn;
            sm.bufA[(6 + 6 * b + 0) * SS + tid] = cs;
            sincosf(f * py, &sn, &cs);
            sm.bufA[(3 + 6 * b + 1) * SS + tid] = sn;
            sm.bufA[(6 + 6 * b + 1) * SS + tid] = cs;
            sincosf(f * pz, &sn, &cs);
            sm.bufA[(3 + 6 * b + 2) * SS + tid] = sn;
            sm.bufA[(6 + 6 * b + 2) * SS + tid] = cs;
        }
    }
    __syncthreads();

    // ======== Layer 1: H^T = relu(W1^T @ ENC), warp-uniform weights ========
    {
        F2 acc[4][8];   // [sample][colpair]
#pragma unroll
        for (int cp = 0; cp < 8; cp++) {
            const F2 bb = f2mk(b1c[col0 + 2 * cp], b1c[col0 + 2 * cp + 1]);
#pragma unroll
            for (int s = 0; s < 4; s++) acc[s][cp] = bb;
        }
#pragma unroll 7
        for (int k = 0; k < D_ENC; k++) {
            const float4 av = *(const float4*)&sm.bufA[k * SS + s0];
            const float4 w0 = *(const float4*)&W1c[k * HID + col0];
            const float4 w1 = *(const float4*)&W1c[k * HID + col0 + 4];
            const float4 w2 = *(const float4*)&W1c[k * HID + col0 + 8];
            const float4 w3 = *(const float4*)&W1c[k * HID + col0 + 12];
            const F2 wp[8] = {f2mk(w0.x, w0.y), f2mk(w0.z, w0.w),
                              f2mk(w1.x, w1.y), f2mk(w1.z, w1.w),
                              f2mk(w2.x, w2.y), f2mk(w2.z, w2.w),
                              f2mk(w3.x, w3.y), f2mk(w3.z, w3.w)};
            const float as[4] = {av.x, av.y, av.z, av.w};
#pragma unroll
            for (int s = 0; s < 4; s++) {
                const F2 ad = f2dup(as[s]);
#pragma unroll
                for (int cp = 0; cp < 8; cp++) fma2(acc[s][cp], ad, wp[cp]);
            }
        }
        __syncthreads();   // all ENC reads done before overwriting bufA
#pragma unroll
        for (int cp = 0; cp < 8; cp++) {
            float4 v0, v1;
            v0.x = fmaxf(acc[0][cp].f.x, 0.f); v1.x = fmaxf(acc[0][cp].f.y, 0.f);
            v0.y = fmaxf(acc[1][cp].f.x, 0.f); v1.y = fmaxf(acc[1][cp].f.y, 0.f);
            v0.z = fmaxf(acc[2][cp].f.x, 0.f); v1.z = fmaxf(acc[2][cp].f.y, 0.f);
            v0.w = fmaxf(acc[3][cp].f.x, 0.f); v1.w = fmaxf(acc[3][cp].f.y, 0.f);
            *(float4*)&sm.bufA[(col0 + 2 * cp) * SS + s0] = v0;
            *(float4*)&sm.bufA[(col0 + 2 * cp + 1) * SS + s0] = v1;
        }
    }
    __syncthreads();

    // ======== Layers 2+3+4 fully register-resident, one sample per thread ====
    // ---- Layer 2: o[16] = W2^T @ h  (h read from bufA column tid) ----
    F2 o2[8];
#pragma unroll
    for (int cp = 0; cp < 8; cp++) o2[cp] = f2mk(b2c[2 * cp], b2c[2 * cp + 1]);
#pragma unroll 8
    for (int k = 0; k < HID; k++) {
        const F2 hd = f2dup(sm.bufA[k * SS + tid]);
#pragma unroll
        for (int q = 0; q < 4; q++) {
            const float4 w = *(const float4*)&W2c[k * 16 + 4 * q];
            fma2(o2[2 * q + 0], hd, f2mk(w.x, w.y));
            fma2(o2[2 * q + 1], hd, f2mk(w.z, w.w));
        }
    }

    // ---- Layer 3: g[64] = base + V1a^T @ rgb_feat (all registers) ----
    F2 g[32];
#pragma unroll
    for (int cp = 0; cp < 32; cp++)
        g[cp] = f2mk(sm.basev[2 * cp], sm.basev[2 * cp + 1]);
#pragma unroll
    for (int k = 0; k < FEAT; k++) {
        const int col = k + 1;                       // rgb_feat index
        const float fv = (col & 1) ? o2[col >> 1].f.y : o2[col >> 1].f.x;
        const F2 ad = f2dup(fv);
#pragma unroll
        for (int q = 0; q < 16; q++) {
            const float4 w = *(const float4*)&V1c[k * HID + 4 * q];
            fma2(g[2 * q + 0], ad, f2mk(w.x, w.y));
            fma2(g[2 * q + 1], ad, f2mk(w.z, w.w));
        }
    }

    // ---- Layer 4: rgb = sigmoid(relu(g) @ V2 + c2)  (uniform LDCU weights) ----
    float r0 = c2c[0], r1 = c2c[1], r2 = c2c[2];
#pragma unroll 8
    for (int k = 0; k < HID; k++) {
        const float gv = fmaxf((k & 1) ? g[k >> 1].f.y : g[k >> 1].f.x, 0.f);
        r0 += gv * V2c[k * 3 + 0];
        r1 += gv * V2c[k * 3 + 1];
        r2 += gv * V2c[k * 3 + 2];
    }
    r0 = 1.f / (1.f + expf(-r0));
    r1 = 1.f / (1.f + expf(-r1));
    r2 = 1.f / (1.f + expf(-r2));

    // ---- compositing ----
    {
        const float sigma = fmaxf(o2[0].f.x, 0.f);
        const float dtv = g_dt;
        const float om = expf(-sigma * dtv);
        const float alpha = 1.f - om;

        // warp-level exclusive product scan
        float e = __shfl_up_sync(0xffffffffu, om, 1);
        if (lane == 0) e = 1.f;
        float x = e;
#pragma unroll
        for (int off = 1; off < 32; off <<= 1) {
            const float v = __shfl_up_sync(0xffffffffu, x, off);
            if (lane >= off) x *= v;
        }
        if (lane == 31) sm.wagg[warp] = x * om;
        __syncthreads();
        float pre = 1.f;
#pragma unroll
        for (int w2 = 0; w2 < 4; w2++)
            if (w2 < warp) pre *= sm.wagg[w2];
        const float Texcl = pre * x;

        const bool active = (Texcl > 1e-4f);
        const float w = active ? Texcl * alpha : 0.f;

        float cr = w * r0, cg2 = w * r1, cb = w * r2;
        float tf = active ? om : 1.f;
#pragma unroll
        for (int off = 16; off; off >>= 1) {
            cr  += __shfl_down_sync(0xffffffffu, cr,  off);
            cg2 += __shfl_down_sync(0xffffffffu, cg2, off);
            cb  += __shfl_down_sync(0xffffffffu, cb,  off);
            tf  *= __shfl_down_sync(0xffffffffu, tf,  off);
        }
        if (lane == 0) {
            sm.red[warp * 4 + 0] = cr;
            sm.red[warp * 4 + 1] = cg2;
            sm.red[warp * 4 + 2] = cb;
            sm.red[warp * 4 + 3] = tf;
        }
        __syncthreads();
        if (tid == 0) {
            out[r * 3 + 0] = sm.red[0] + sm.red[4] + sm.red[8] + sm.red[12];
            out[r * 3 + 1] = sm.red[1] + sm.red[5] + sm.red[9] + sm.red[13];
            out[r * 3 + 2] = sm.red[2] + sm.red[6] + sm.red[10] + sm.red[14];
            out[3 * N + r] = sm.red[3] * sm.red[7] * sm.red[11] * sm.red[15];
        }
    }
}

// ---------------------------------------------------------------------------
extern "C" void kernel_launch(void* const* d_in, const int* in_sizes, int n_in,
                              void* d_out, int out_size) {
    const float* orig = (const float*)d_in[0];
    const float* dirs = (const float*)d_in[1];
    const float* tmin = (const float*)d_in[2];
    const float* tmax = (const float*)d_in[3];
    const float* W1   = (const float*)d_in[4];
    const float* b1   = (const float*)d_in[5];
    const float* W2   = (const float*)d_in[6];
    const float* b2   = (const float*)d_in[7];
    const float* V1   = (const float*)d_in[8];
    const float* c1   = (const float*)d_in[9];
    const float* V2   = (const float*)d_in[10];
    const float* c2   = (const float*)d_in[11];
    float* out = (float*)d_out;
    const int N = in_sizes[2];

    cudaMemcpyToSymbolAsync(W1c, W1, D_ENC * HID * sizeof(float), 0, cudaMemcpyDeviceToDevice, 0);
    cudaMemcpyToSymbolAsync(b1c, b1, HID * sizeof(float), 0, cudaMemcpyDeviceToDevice, 0);
    cudaMemcpyToSymbolAsync(W2c, W2, HID * 16 * sizeof(float), 0, cudaMemcpyDeviceToDevice, 0);
    cudaMemcpyToSymbolAsync(b2c, b2, 16 * sizeof(float), 0, cudaMemcpyDeviceToDevice, 0);
    cudaMemcpyToSymbolAsync(V1c, V1, FEAT * HID * sizeof(float), 0, cudaMemcpyDeviceToDevice, 0);
    cudaMemcpyToSymbolAsync(V2c, V2, HID * 3 * sizeof(float), 0, cudaMemcpyDeviceToDevice, 0);
    cudaMemcpyToSymbolAsync(c2c, c2, 3 * sizeof(float), 0, cudaMemcpyDeviceToDevice, 0);

    reduce_dt_kernel<<<1, 256>>>(tmin, tmax, N);
    raymarch_kernel<<<N, SS, sizeof(SmemT)>>>(orig, dirs, tmin, tmax,
                                              V1, c1, out, N);
}

// round 8
// speedup vs baseline: 1.9557x; 1.2469x over previous
#include <cuda_runtime.h>
#include <math.h>

#define SS 128
#define POS_BANDS 10
#define D_ENC 63
#define D_VD 27
#define HID 64
#define FEAT 15

__device__ float g_dt;

// ---- weights in constant memory (uniform-const port, off the L1tex path) ----
__constant__ float W1c[D_ENC * HID];
__constant__ float b1c[HID];
__constant__ float W2c[HID * 16];
__constant__ float b2c[16];
__constant__ float V1c[FEAT * HID];    // rows 0..14 only
__constant__ float V2c[HID * 3];
__constant__ float c2c[3];

// ---------------- packed f32x2 FMA ----------------
struct F2 { union { float2 f; unsigned long long u; }; };
__device__ __forceinline__ F2 f2mk(float x, float y) { F2 r; r.f.x = x; r.f.y = y; return r; }
__device__ __forceinline__ F2 f2dup(float x) { return f2mk(x, x); }
__device__ __forceinline__ void fma2(F2& d, const F2 a, const F2 b) {
    asm("fma.rn.f32x2 %0, %1, %2, %0;" : "+l"(d.u) : "l"(a.u), "l"(b.u));
}

// ---------------------------------------------------------------------------
__global__ void reduce_dt_kernel(const float* __restrict__ tmin,
                                 const float* __restrict__ tmax, int n) {
    __shared__ float sh[256];
    float s = 0.f;
    for (int i = threadIdx.x; i < n; i += 256) s += tmax[i] - tmin[i];
    sh[threadIdx.x] = s;
    __syncthreads();
    for (int o = 128; o > 0; o >>= 1) {
        if (threadIdx.x < o) sh[threadIdx.x] += sh[threadIdx.x + o];
        __syncthreads();
    }
    if (threadIdx.x == 0) g_dt = sh[0] / (float)n / (float)SS;
}

// ---------------------------------------------------------------------------
struct __align__(16) SmemT {
    float bufA[64 * SS];   // 32 KB: ENC^T (rows 0..62) -> H^T (rows 0..63)
    float basev[64];       // c1 + vd_enc @ V1[15:42]
    float vd[28];
    float wagg[4];
    float red[16];
};

__global__ void __launch_bounds__(SS, 4)
raymarch_kernel(const float* __restrict__ orig, const float* __restrict__ dirs,
                const float* __restrict__ tmin, const float* __restrict__ tmax,
                const float* __restrict__ V1, const float* __restrict__ c1,
                float* __restrict__ out, int N) {
    extern __shared__ char smem_raw[];
    SmemT& sm = *reinterpret_cast<SmemT*>(smem_raw);
    const int r = blockIdx.x;
    const int tid = threadIdx.x;
    const int lane = tid & 31;
    const int warp = tid >> 5;
    const int s0 = lane * 4;        // layer-1 tile: 4 samples per lane
    const int col0 = warp * 16;     // layer-1 tile: 16 columns per warp (uniform)

    const float dx = dirs[r * 3 + 0], dy = dirs[r * 3 + 1], dz = dirs[r * 3 + 2];
    const float inv = 1.f / (sqrtf(dx * dx + dy * dy + dz * dz) + 1e-8f);
    if (tid < D_VD) {
        const int p = tid / 3, c = tid % 3;
        float v = ((c == 0) ? dx : (c == 1) ? dy : dz) * inv;
        float val;
        if (p == 0) val = v;
        else {
            const int band = (p - 1) >> 1;
            float sn, cs;
            sincosf(v * (float)(1 << band), &sn, &cs);
            val = ((p - 1) & 1) ? cs : sn;
        }
        sm.vd[tid] = val;
    }
    __syncthreads();

    // ---- base = c1 + vd_enc @ V1[15:42]  (per-ray constant; coalesced LDG) ----
    if (tid < HID) {
        float acc = c1[tid];
#pragma unroll
        for (int k = 0; k < D_VD; k++) acc += sm.vd[k] * V1[(FEAT + k) * HID + tid];
        sm.basev[tid] = acc;
    }

    // ---- positional encoding -> ENC^T in bufA rows 0..62 ----
    // Bands via angle-doubling: (c+is)^2 -> exactly doubles the angle.
    {
        const float t0 = tmin[r], t1 = tmax[r];
        const float tt = t0 + (float)tid * (1.f / (SS - 1)) * (t1 - t0);
        const float p3[3] = {orig[r * 3 + 0] + dx * tt,
                             orig[r * 3 + 1] + dy * tt,
                             orig[r * 3 + 2] + dz * tt};
#pragma unroll
        for (int c = 0; c < 3; c++) {
            const float pv = p3[c];
            sm.bufA[c * SS + tid] = pv;
            float s, cz;
            sincosf(pv, &s, &cz);          // band 0 (f = 1), precise
            sm.bufA[(3 + c) * SS + tid] = s;
            sm.bufA[(6 + c) * SS + tid] = cz;
#pragma unroll
            for (int b = 1; b < POS_BANDS; b++) {
                const float s2 = 2.f * s * cz;           // sin(2a) = 2 sin cos
                const float c2 = fmaf(-2.f * s, s, 1.f); // cos(2a) = 1 - 2 sin^2
                s = s2; cz = c2;
                sm.bufA[(3 + 6 * b + c) * SS + tid] = s;
                sm.bufA[(6 + 6 * b + c) * SS + tid] = cz;
            }
        }
    }
    __syncthreads();

    // ======== Layer 1: H^T = relu(W1^T @ ENC), warp-uniform weights ========
    {
        F2 acc[4][8];   // [sample][colpair]
#pragma unroll
        for (int cp = 0; cp < 8; cp++) {
            const F2 bb = f2mk(b1c[col0 + 2 * cp], b1c[col0 + 2 * cp + 1]);
#pragma unroll
            for (int s = 0; s < 4; s++) acc[s][cp] = bb;
        }
#pragma unroll 7
        for (int k = 0; k < D_ENC; k++) {
            const float4 av = *(const float4*)&sm.bufA[k * SS + s0];
            const float4 w0 = *(const float4*)&W1c[k * HID + col0];
            const float4 w1 = *(const float4*)&W1c[k * HID + col0 + 4];
            const float4 w2 = *(const float4*)&W1c[k * HID + col0 + 8];
            const float4 w3 = *(const float4*)&W1c[k * HID + col0 + 12];
            const F2 wp[8] = {f2mk(w0.x, w0.y), f2mk(w0.z, w0.w),
                              f2mk(w1.x, w1.y), f2mk(w1.z, w1.w),
                              f2mk(w2.x, w2.y), f2mk(w2.z, w2.w),
                              f2mk(w3.x, w3.y), f2mk(w3.z, w3.w)};
            const float as[4] = {av.x, av.y, av.z, av.w};
#pragma unroll
            for (int s = 0; s < 4; s++) {
                const F2 ad = f2dup(as[s]);
#pragma unroll
                for (int cp = 0; cp < 8; cp++) fma2(acc[s][cp], ad, wp[cp]);
            }
        }
        __syncthreads();   // all ENC reads done before overwriting bufA
#pragma unroll
        for (int cp = 0; cp < 8; cp++) {
            float4 v0, v1;
            v0.x = fmaxf(acc[0][cp].f.x, 0.f); v1.x = fmaxf(acc[0][cp].f.y, 0.f);
            v0.y = fmaxf(acc[1][cp].f.x, 0.f); v1.y = fmaxf(acc[1][cp].f.y, 0.f);
            v0.z = fmaxf(acc[2][cp].f.x, 0.f); v1.z = fmaxf(acc[2][cp].f.y, 0.f);
            v0.w = fmaxf(acc[3][cp].f.x, 0.f); v1.w = fmaxf(acc[3][cp].f.y, 0.f);
            *(float4*)&sm.bufA[(col0 + 2 * cp) * SS + s0] = v0;
            *(float4*)&sm.bufA[(col0 + 2 * cp + 1) * SS + s0] = v1;
        }
    }
    __syncthreads();

    // ======== Layers 2+3+4 fully register-resident, one sample per thread ====
    // ---- Layer 2: o[16] = W2^T @ h  (h read from bufA column tid) ----
    F2 o2[8];
#pragma unroll
    for (int cp = 0; cp < 8; cp++) o2[cp] = f2mk(b2c[2 * cp], b2c[2 * cp + 1]);
#pragma unroll 8
    for (int k = 0; k < HID; k++) {
        const F2 hd = f2dup(sm.bufA[k * SS + tid]);
#pragma unroll
        for (int q = 0; q < 4; q++) {
            const float4 w = *(const float4*)&W2c[k * 16 + 4 * q];
            fma2(o2[2 * q + 0], hd, f2mk(w.x, w.y));
            fma2(o2[2 * q + 1], hd, f2mk(w.z, w.w));
        }
    }

    // ---- Layer 3: g[64] = base + V1a^T @ rgb_feat (all registers) ----
    F2 g[32];
#pragma unroll
    for (int cp = 0; cp < 32; cp++)
        g[cp] = f2mk(sm.basev[2 * cp], sm.basev[2 * cp + 1]);
#pragma unroll
    for (int k = 0; k < FEAT; k++) {
        const int col = k + 1;                       // rgb_feat index
        const float fv = (col & 1) ? o2[col >> 1].f.y : o2[col >> 1].f.x;
        const F2 ad = f2dup(fv);
#pragma unroll
        for (int q = 0; q < 16; q++) {
            const float4 w = *(const float4*)&V1c[k * HID + 4 * q];
            fma2(g[2 * q + 0], ad, f2mk(w.x, w.y));
            fma2(g[2 * q + 1], ad, f2mk(w.z, w.w));
        }
    }

    // ---- Layer 4: rgb = sigmoid(relu(g) @ V2 + c2)  (uniform LDCU weights) ----
    float r0 = c2c[0], r1 = c2c[1], r2 = c2c[2];
#pragma unroll 8
    for (int k = 0; k < HID; k++) {
        const float gv = fmaxf((k & 1) ? g[k >> 1].f.y : g[k >> 1].f.x, 0.f);
        r0 += gv * V2c[k * 3 + 0];
        r1 += gv * V2c[k * 3 + 1];
        r2 += gv * V2c[k * 3 + 2];
    }
    r0 = 1.f / (1.f + __expf(-r0));
    r1 = 1.f / (1.f + __expf(-r1));
    r2 = 1.f / (1.f + __expf(-r2));

    // ---- compositing ----
    {
        const float sigma = fmaxf(o2[0].f.x, 0.f);
        const float dtv = g_dt;
        const float om = __expf(-sigma * dtv);
        const float alpha = 1.f - om;

        // warp-level exclusive product scan
        float e = __shfl_up_sync(0xffffffffu, om, 1);
        if (lane == 0) e = 1.f;
        float x = e;
#pragma unroll
        for (int off = 1; off < 32; off <<= 1) {
            const float v = __shfl_up_sync(0xffffffffu, x, off);
            if (lane >= off) x *= v;
        }
        if (lane == 31) sm.wagg[warp] = x * om;
        __syncthreads();
        float pre = 1.f;
#pragma unroll
        for (int w2 = 0; w2 < 4; w2++)
            if (w2 < warp) pre *= sm.wagg[w2];
        const float Texcl = pre * x;

        const bool active = (Texcl > 1e-4f);
        const float w = active ? Texcl * alpha : 0.f;

        float cr = w * r0, cg2 = w * r1, cb = w * r2;
        float tf = active ? om : 1.f;
#pragma unroll
        for (int off = 16; off; off >>= 1) {
            cr  += __shfl_down_sync(0xffffffffu, cr,  off);
            cg2 += __shfl_down_sync(0xffffffffu, cg2, off);
            cb  += __shfl_down_sync(0xffffffffu, cb,  off);
            tf  *= __shfl_down_sync(0xffffffffu, tf,  off);
        }
        if (lane == 0) {
            sm.red[warp * 4 + 0] = cr;
            sm.red[warp * 4 + 1] = cg2;
            sm.red[warp * 4 + 2] = cb;
            sm.red[warp * 4 + 3] = tf;
        }
        __syncthreads();
        if (tid == 0) {
            out[r * 3 + 0] = sm.red[0] + sm.red[4] + sm.red[8] + sm.red[12];
            out[r * 3 + 1] = sm.red[1] + sm.red[5] + sm.red[9] + sm.red[13];
            out[r * 3 + 2] = sm.red[2] + sm.red[6] + sm.red[10] + sm.red[14];
            out[3 * N + r] = sm.red[3] * sm.red[7] * sm.red[11] * sm.red[15];
        }
    }
}

// ---------------------------------------------------------------------------
extern "C" void kernel_launch(void* const* d_in, const int* in_sizes, int n_in,
                              void* d_out, int out_size) {
    const float* orig = (const float*)d_in[0];
    const float* dirs = (const float*)d_in[1];
    const float* tmin = (const float*)d_in[2];
    const float* tmax = (const float*)d_in[3];
    const float* W1   = (const float*)d_in[4];
    const float* b1   = (const float*)d_in[5];
    const float* W2   = (const float*)d_in[6];
    const float* b2   = (const float*)d_in[7];
    const float* V1   = (const float*)d_in[8];
    const float* c1   = (const float*)d_in[9];
    const float* V2   = (const float*)d_in[10];
    const float* c2   = (const float*)d_in[11];
    float* out = (float*)d_out;
    const int N = in_sizes[2];

    cudaMemcpyToSymbolAsync(W1c, W1, D_ENC * HID * sizeof(float), 0, cudaMemcpyDeviceToDevice, 0);
    cudaMemcpyToSymbolAsync(b1c, b1, HID * sizeof(float), 0, cudaMemcpyDeviceToDevice, 0);
    cudaMemcpyToSymbolAsync(W2c, W2, HID * 16 * sizeof(float), 0, cudaMemcpyDeviceToDevice, 0);
    cudaMemcpyToSymbolAsync(b2c, b2, 16 * sizeof(float), 0, cudaMemcpyDeviceToDevice, 0);
    cudaMemcpyToSymbolAsync(V1c, V1, FEAT * HID * sizeof(float), 0, cudaMemcpyDeviceToDevice, 0);
    cudaMemcpyToSymbolAsync(V2c, V2, HID * 3 * sizeof(float), 0, cudaMemcpyDeviceToDevice, 0);
    cudaMemcpyToSymbolAsync(c2c, c2, 3 * sizeof(float), 0, cudaMemcpyDeviceToDevice, 0);

    reduce_dt_kernel<<<1, 256>>>(tmin, tmax, N);
    raymarch_kernel<<<N, SS, sizeof(SmemT)>>>(orig, dirs, tmin, tmax,
                                              V1, c1, out, N);
}